// round 7
// baseline (speedup 1.0000x reference)
#include <cuda_runtime.h>

// Problem constants (fixed by the reference)
#define B_     4
#define N_     4096
#define E_     128
#define CACHE_ 32
#define NK_    4
#define CE_    32      // channels per unit (E / NK)
#define M_     128     // N / CACHE
#define BNE_   (B_*N_*E_)
#define KP_    16      // packed channel pairs per warp (all 32 channels)

// Inter-layer scratch (device globals: no allocation in kernel_launch)
__device__ float g_x [BNE_];
__device__ float g_xa[BNE_];

typedef unsigned long long u64;

__device__ __forceinline__ float tanh_fast(float x) {
    float y;
    asm("tanh.approx.f32 %0, %1;" : "=f"(y) : "f"(x));
    return y;
}
__device__ __forceinline__ u64 pk(float lo, float hi) {
    u64 r; asm("mov.b64 %0, {%1, %2};" : "=l"(r) : "f"(lo), "f"(hi)); return r;
}
__device__ __forceinline__ void upk(u64 x, float& lo, float& hi) {
    asm("mov.b64 {%0, %1}, %2;" : "=f"(lo), "=f"(hi) : "l"(x));
}
__device__ __forceinline__ u64 fma2(u64 a, u64 b, u64 c) {
    u64 d; asm("fma.rn.f32x2 %0, %1, %2, %3;" : "=l"(d) : "l"(a), "l"(b), "l"(c)); return d;
}
__device__ __forceinline__ u64 mul2(u64 a, u64 b) {
    u64 d; asm("mul.rn.f32x2 %0, %1, %2;" : "=l"(d) : "l"(a), "l"(b)); return d;
}
__device__ __forceinline__ u64 add2(u64 a, u64 b) {
    u64 d; asm("add.rn.f32x2 %0, %1, %2;" : "=l"(d) : "l"(a), "l"(b)); return d;
}

// ONE warp per (b,g,n) unit — no cross-warp sync anywhere in the recurrence.
// lane = row-in-group; all 32 channels live in-register as 16 packed pairs.
// Rescaled state: u2 = (xi/2)/0.9^j, v2 = (xa/2)/0.9^j so
//   v' = v + c_j*F ; u' = u + 0.1*v' ; T(true) = sc*(u + sim*u_j).
// Full running dots (true scale) packed: AB2=(Ax,Bx), ab2=(Aa,Ba).
// Weights from smem as one 16B vector per pair: sW4[2k]=(Wi_2k,Wi_2k+1),
// sW4[2k+1]=(Wj_2k,Wj_2k+1)  ->  single LDS.128 feeds both dot FMAs.
__global__ void __launch_bounds__(32, 14)
ncn_layer(const float* __restrict__ X, const float* __restrict__ XA,
          const float* __restrict__ W,         // 256 floats: Wi[4][32], Wj[4][32]
          float* __restrict__ YX, float* __restrict__ YA,
          int s)                                // group-index stride (0 or 1)
{
    __shared__ float tile[CACHE_][CACHE_ + 1];
    __shared__ __align__(16) u64 sW4[2 * KP_];  // interleaved (Wi2, Wj2) pairs

    const int lane = threadIdx.x;
    const int blk  = blockIdx.x;                // 0 .. 2047
    const int n    = blk & (NK_ - 1);
    const int g    = (blk >> 2) & (M_ - 1);
    const int b    = blk >> 9;

    if (lane < KP_) {
        int c = n * CE_ + 2 * lane;
        sW4[2 * lane]     = pk(W[c],       W[c + 1]);        // (Wi_c0, Wi_c1)
        sW4[2 * lane + 1] = pk(W[E_ + c],  W[E_ + c + 1]);   // (Wj_c0, Wj_c1)
    }
    __syncwarp();

    const long long bBase    = (long long)b * N_ * E_;
    const long long chanBase = (long long)n * CE_ + lane;

    u64 u2[KP_], v2[KP_];

    // ---- gather xi tile (coalesced per row, transpose through smem) ----
    #pragma unroll
    for (int r = 0; r < CACHE_; ++r) {
        int row = ((g + r * s) & (M_ - 1)) * CACHE_ + r;
        tile[r][lane] = X[bBase + (long long)row * E_ + chanBase];
    }
    __syncwarp();
    #pragma unroll
    for (int k = 0; k < KP_; ++k)
        u2[k] = pk(0.5f * tile[lane][2 * k], 0.5f * tile[lane][2 * k + 1]);
    __syncwarp();

    // ---- gather xa tile ----
    #pragma unroll
    for (int r = 0; r < CACHE_; ++r) {
        int row = ((g + r * s) & (M_ - 1)) * CACHE_ + r;
        tile[r][lane] = XA[bBase + (long long)row * E_ + chanBase];
    }
    __syncwarp();
    #pragma unroll
    for (int k = 0; k < KP_; ++k)
        v2[k] = pk(0.5f * tile[lane][2 * k], 0.5f * tile[lane][2 * k + 1]);

    const u64 K09 = pk(0.9f, 0.9f);
    const u64 K01 = pk(0.1f, 0.1f);
    const u64 Z   = pk(0.f, 0.f);
    const ulonglong2* sWv = reinterpret_cast<const ulonglong2*>(sW4);

    // ---- initial full running dots (true scale = 2 * half-scale dot) ----
    u64 AB2, ab2;   // (Ax,Bx), (Aa,Ba)
    {
        u64 ax = Z, bx = Z, aa = Z, ba = Z;
        #pragma unroll
        for (int k = 0; k < KP_; ++k) {
            ulonglong2 ww = sWv[k];             // (Wi2, Wj2)
            ax = fma2(u2[k], ww.x, ax);
            bx = fma2(u2[k], ww.y, bx);
            aa = fma2(v2[k], ww.x, aa);
            ba = fma2(v2[k], ww.y, ba);
        }
        float l, h, Ax, Bx, Aa, Ba;
        upk(ax, l, h); Ax = 2.f * (l + h);
        upk(bx, l, h); Bx = 2.f * (l + h);
        upk(aa, l, h); Aa = 2.f * (l + h);
        upk(ba, l, h); Ba = 2.f * (l + h);
        AB2 = pk(Ax, Bx);
        ab2 = pk(Aa, Ba);
    }

    float sc = 1.0f;                  // 0.9^j
    float cj = 0.05f / 0.9f;          // 0.05 / 0.9^(j+1)

    // ---- 32-step recurrence (no barriers, warp-private) ----
    #pragma unroll 1
    for (int j = 0; j < CACHE_; ++j) {
        float Ax, Bx; upk(AB2, Ax, Bx);
        float sim = Ax + __shfl_sync(0xffffffffu, Bx, j);

        u64 sim2 = pk(sim, sim);
        u64 s2   = pk(sc, sc);
        u64 c2   = pk(cj, cj);
        u64 SA = Z, SB = Z, DA = Z, DB = Z;     // pair-packed dot partials
        #pragma unroll
        for (int k = 0; k < KP_; ++k) {
            u64 uj = __shfl_sync(0xffffffffu, u2[k], j);    // pre-update row j
            u64 T  = mul2(s2, fma2(sim2, uj, u2[k]));       // true-scale T
            float t0, t1; upk(T, t0, t1);
            u64 F = pk(tanh_fast(t0), tanh_fast(t1));
            ulonglong2 ww = sWv[k];                          // one LDS.128
            if (k & 1) { SB = fma2(F, ww.x, SB); DB = fma2(F, ww.y, DB); }
            else       { SA = fma2(F, ww.x, SA); DA = fma2(F, ww.y, DA); }
            v2[k] = fma2(c2,  F,     v2[k]);                // ~xa update
            u2[k] = fma2(K01, v2[k], u2[k]);                // ~xi update
        }
        float l, h, SF, DF;
        { u64 q = add2(SA, SB); upk(q, l, h); SF = l + h; }
        { u64 q = add2(DA, DB); upk(q, l, h); DF = l + h; }
        u64 S2 = pk(SF, DF);

        ab2 = fma2(ab2, K09, mul2(S2, K01));                // (Aa,Ba)'
        AB2 = fma2(AB2, K09, mul2(ab2, K01));               // (Ax,Bx)'

        sc *= 0.9f;
        cj *= (1.0f / 0.9f);
    }

    const float fscale = 2.0f * sc;   // undo half-scale and 0.9^32 rescale

    // ---- scatter yi ----
    __syncwarp();
    #pragma unroll
    for (int k = 0; k < KP_; ++k) {
        float l, h; upk(u2[k], l, h);
        tile[lane][2 * k]     = fscale * l;
        tile[lane][2 * k + 1] = fscale * h;
    }
    __syncwarp();
    #pragma unroll
    for (int r = 0; r < CACHE_; ++r) {
        int row = ((g + r * s) & (M_ - 1)) * CACHE_ + r;
        YX[bBase + (long long)row * E_ + chanBase] = tile[r][lane];
    }
    __syncwarp();

    // ---- scatter ya ----
    #pragma unroll
    for (int k = 0; k < KP_; ++k) {
        float l, h; upk(v2[k], l, h);
        tile[lane][2 * k]     = fscale * l;
        tile[lane][2 * k + 1] = fscale * h;
    }
    __syncwarp();
    #pragma unroll
    for (int r = 0; r < CACHE_; ++r) {
        int row = ((g + r * s) & (M_ - 1)) * CACHE_ + r;
        YA[bBase + (long long)row * E_ + chanBase] = tile[r][lane];
    }
}

extern "C" void kernel_launch(void* const* d_in, const int* in_sizes, int n_in,
                              void* d_out, int out_size) {
    const float* x  = (const float*)d_in[0];
    const float* xa = (const float*)d_in[1];
    const float* W  = (const float*)d_in[2];
    float* out = (float*)d_out;

    float *gx = nullptr, *gxa = nullptr;
    cudaGetSymbolAddress((void**)&gx,  g_x);
    cudaGetSymbolAddress((void**)&gxa, g_xa);

    dim3 grid(B_ * M_ * NK_);   // 2048 one-warp blocks
    dim3 block(32);

    // Layer 0: stage shift s = 0 (contiguous groups)
    ncn_layer<<<grid, block>>>(x, xa, W, gx, gxa, 0);
    // Layer 1: stage shift s = 1 (block = (g + o) % m), writes final output
    ncn_layer<<<grid, block>>>(gx, gxa, W + 2 * E_, out, out + BNE_, 1);
}

// round 8
// speedup vs baseline: 1.4216x; 1.4216x over previous
#include <cuda_runtime.h>

// Problem constants (fixed by the reference)
#define B_     4
#define N_     4096
#define E_     128
#define CACHE_ 32
#define NK_    4
#define CE_    32      // channels per unit (E / NK)
#define M_     128     // N / CACHE
#define BNE_   (B_*N_*E_)
#define NW_    4       // warps per unit
#define CPW_   8       // channels per warp
#define KP_    4       // packed channel pairs per warp

// Inter-layer scratch (device globals: no allocation in kernel_launch)
__device__ float g_x [BNE_];
__device__ float g_xa[BNE_];

typedef unsigned long long u64;

__device__ __forceinline__ float tanh_fast(float x) {
    float y;
    asm("tanh.approx.f32 %0, %1;" : "=f"(y) : "f"(x));
    return y;
}
__device__ __forceinline__ u64 pk(float lo, float hi) {
    u64 r; asm("mov.b64 %0, {%1, %2};" : "=l"(r) : "f"(lo), "f"(hi)); return r;
}
__device__ __forceinline__ void upk(u64 x, float& lo, float& hi) {
    asm("mov.b64 {%0, %1}, %2;" : "=f"(lo), "=f"(hi) : "l"(x));
}
__device__ __forceinline__ u64 fma2(u64 a, u64 b, u64 c) {
    u64 d; asm("fma.rn.f32x2 %0, %1, %2, %3;" : "=l"(d) : "l"(a), "l"(b), "l"(c)); return d;
}
__device__ __forceinline__ u64 mul2(u64 a, u64 b) {
    u64 d; asm("mul.rn.f32x2 %0, %1, %2;" : "=l"(d) : "l"(a), "l"(b)); return d;
}
__device__ __forceinline__ u64 add2(u64 a, u64 b) {
    u64 d; asm("add.rn.f32x2 %0, %1, %2;" : "=l"(d) : "l"(a), "l"(b)); return d;
}

// 4 warps per (b,g,n) unit. lane = row-in-group. Warp w owns channels
// [w*8, w*8+8) as 4 packed f32 pairs. Rescaled state:
//   u2=(xi/2)/0.9^j, v2=(xa/2)/0.9^j ; v'=v+c_j*F ; u'=u+0.1*v' ;
//   T(true) = sc*(u2 + sim*u2_j).
// LINEAR-SPLIT partial running dots per warp (true scale):
//   X2w=(Ax_w,Bx_w), A2w=(Aa_w,Ba_w); warp updates them with its OWN
//   S2_w=(SF_w,DF_w) only. sim totals come from the per-step exchange:
//   sim[lane] = sum_w Ax_w[lane] + sum_w Bx_w[j].
// X'_w = .9X_w+.09A_w+.01S_w with P2 = .9X+.09A precomputed off-chain.
// One __syncthreads per step. Weights from smem (LDS.128 per pair).
__global__ void __launch_bounds__(128, 8)
ncn_layer(const float* __restrict__ X, const float* __restrict__ XA,
          const float* __restrict__ W,         // 256 floats: Wi[4][32], Wj[4][32]
          float* __restrict__ YX, float* __restrict__ YA,
          int s)                                // group-index stride (0 or 1)
{
    __shared__ float tile[CACHE_][CACHE_ + 1];
    __shared__ u64 ebuf[2][NW_][CACHE_];        // [parity][warp][lane] = (Ax_w,Bx_w)
    __shared__ __align__(16) u64 sW4[2 * (CE_ / 2)];  // (Wi2,Wj2) interleaved, 16 pairs

    const int t    = threadIdx.x;
    const int w    = t >> 5;                    // warp in block (0..3)
    const int lane = t & 31;                    // row-in-group
    const int blk  = blockIdx.x;                // 0 .. 2047
    const int n    = blk & (NK_ - 1);
    const int g    = (blk >> 2) & (M_ - 1);
    const int b    = blk >> 9;

    if (t < CE_ / 2) {
        int c = n * CE_ + 2 * t;
        sW4[2 * t]     = pk(W[c],      W[c + 1]);       // (Wi_c0, Wi_c1)
        sW4[2 * t + 1] = pk(W[E_ + c], W[E_ + c + 1]);  // (Wj_c0, Wj_c1)
    }

    const long long bBase    = (long long)b * N_ * E_;
    const long long chanBase = (long long)n * CE_ + lane;
    const int cw = w * CPW_;                    // this warp's first channel
    const ulonglong2* sWv = reinterpret_cast<const ulonglong2*>(sW4);
    const int kw = cw >> 1;                     // first pair index for this warp

    u64 u2[KP_], v2[KP_];

    // ---- gather xi tile: warp w loads rows [w*8, w*8+8), coalesced ----
    #pragma unroll
    for (int r = 0; r < CPW_; ++r) {
        int rr  = cw + r;
        int row = ((g + rr * s) & (M_ - 1)) * CACHE_ + rr;
        tile[rr][lane] = X[bBase + (long long)row * E_ + chanBase];
    }
    __syncthreads();
    #pragma unroll
    for (int k = 0; k < KP_; ++k)
        u2[k] = pk(0.5f * tile[lane][cw + 2 * k], 0.5f * tile[lane][cw + 2 * k + 1]);
    __syncthreads();

    // ---- gather xa tile ----
    #pragma unroll
    for (int r = 0; r < CPW_; ++r) {
        int rr  = cw + r;
        int row = ((g + rr * s) & (M_ - 1)) * CACHE_ + rr;
        tile[rr][lane] = XA[bBase + (long long)row * E_ + chanBase];
    }
    __syncthreads();
    #pragma unroll
    for (int k = 0; k < KP_; ++k)
        v2[k] = pk(0.5f * tile[lane][cw + 2 * k], 0.5f * tile[lane][cw + 2 * k + 1]);

    const u64 K09  = pk(0.9f,  0.9f);
    const u64 K01  = pk(0.1f,  0.1f);
    const u64 K009 = pk(0.09f, 0.09f);
    const u64 K001 = pk(0.01f, 0.01f);
    const u64 Z    = pk(0.f, 0.f);

    // ---- initial partials: X2w=(Ax_w,Bx_w), A2w=(Aa_w,Ba_w) ----
    u64 X2w, A2w, P2;
    {
        u64 ax = Z, bx = Z, aa = Z, ba = Z;
        #pragma unroll
        for (int k = 0; k < KP_; ++k) {
            ulonglong2 ww = sWv[kw + k];        // (Wi2, Wj2)
            ax = fma2(u2[k], ww.x, ax);
            bx = fma2(u2[k], ww.y, bx);
            aa = fma2(v2[k], ww.x, aa);
            ba = fma2(v2[k], ww.y, ba);
        }
        float l, h, Ax, Bx, Aa, Ba;
        upk(ax, l, h); Ax = 2.f * (l + h);
        upk(bx, l, h); Bx = 2.f * (l + h);
        upk(aa, l, h); Aa = 2.f * (l + h);
        upk(ba, l, h); Ba = 2.f * (l + h);
        X2w = pk(Ax, Bx);
        A2w = pk(Aa, Ba);
        P2  = fma2(X2w, K09, mul2(A2w, K009));  // .9X + .09A for step 0
        ebuf[0][w][lane] = X2w;                 // publish for step 0
    }
    __syncthreads();

    float sc = 1.0f;                  // 0.9^j
    float cj = 0.05f / 0.9f;          // 0.05 / 0.9^(j+1)

    // ---- 32-step recurrence ----
    #pragma unroll 1
    for (int j = 0; j < CACHE_; ++j) {
        const int p = j & 1;

        // totals: sim = sum_w Ax_w[lane] + sum_w Bx_w[j]
        u64 q0 = ebuf[p][0][lane], q1 = ebuf[p][1][lane];
        u64 q2 = ebuf[p][2][lane], q3 = ebuf[p][3][lane];
        u64 r0 = ebuf[p][0][j],    r1 = ebuf[p][1][j];     // broadcast LDS
        u64 r2 = ebuf[p][2][j],    r3 = ebuf[p][3][j];
        u64 qs = add2(add2(q0, q1), add2(q2, q3));
        u64 rs = add2(add2(r0, r1), add2(r2, r3));
        float Axt, Bxt_d, Axt_d, Bxt;
        upk(qs, Axt, Bxt_d);
        upk(rs, Axt_d, Bxt);
        float sim = Axt + Bxt;

        u64 sim2 = pk(sim, sim);
        u64 s2   = pk(sc, sc);
        u64 c2   = pk(cj, cj);
        u64 SA = Z, SB = Z, DA = Z, DB = Z;
        #pragma unroll
        for (int k = 0; k < KP_; ++k) {
            u64 uj = __shfl_sync(0xffffffffu, u2[k], j);    // pre-update row j
            u64 T  = mul2(s2, fma2(sim2, uj, u2[k]));       // true-scale T
            float t0, t1; upk(T, t0, t1);
            u64 F = pk(tanh_fast(t0), tanh_fast(t1));
            ulonglong2 ww = sWv[kw + k];                     // one LDS.128
            if (k & 1) { SB = fma2(F, ww.x, SB); DB = fma2(F, ww.y, DB); }
            else       { SA = fma2(F, ww.x, SA); DA = fma2(F, ww.y, DA); }
            v2[k] = fma2(c2,  F,     v2[k]);                // ~xa update
            u2[k] = fma2(K01, v2[k], u2[k]);                // ~xi update
        }
        float l, h, SF, DF;
        { u64 q = add2(SA, SB); upk(q, l, h); SF = l + h; }
        { u64 q = add2(DA, DB); upk(q, l, h); DF = l + h; }
        u64 S2 = pk(SF, DF);

        X2w = fma2(S2, K001, P2);                           // X' = .9X+.09A+.01S
        ebuf[p ^ 1][w][lane] = X2w;                         // publish (STS.64)
        A2w = fma2(A2w, K09, mul2(S2, K01));                // off-chain
        P2  = fma2(X2w, K09, mul2(A2w, K009));              // for next step
        __syncthreads();                                    // one bar per step

        sc *= 0.9f;
        cj *= (1.0f / 0.9f);
    }

    const float fscale = 2.0f * sc;   // undo half-scale and 0.9^32 rescale

    // ---- scatter yi ----
    #pragma unroll
    for (int k = 0; k < KP_; ++k) {
        float l, h; upk(u2[k], l, h);
        tile[lane][cw + 2 * k]     = fscale * l;
        tile[lane][cw + 2 * k + 1] = fscale * h;
    }
    __syncthreads();
    #pragma unroll
    for (int r = 0; r < CPW_; ++r) {
        int rr  = cw + r;
        int row = ((g + rr * s) & (M_ - 1)) * CACHE_ + rr;
        YX[bBase + (long long)row * E_ + chanBase] = tile[rr][lane];
    }
    __syncthreads();

    // ---- scatter ya ----
    #pragma unroll
    for (int k = 0; k < KP_; ++k) {
        float l, h; upk(v2[k], l, h);
        tile[lane][cw + 2 * k]     = fscale * l;
        tile[lane][cw + 2 * k + 1] = fscale * h;
    }
    __syncthreads();
    #pragma unroll
    for (int r = 0; r < CPW_; ++r) {
        int rr  = cw + r;
        int row = ((g + rr * s) & (M_ - 1)) * CACHE_ + rr;
        YA[bBase + (long long)row * E_ + chanBase] = tile[rr][lane];
    }
}

extern "C" void kernel_launch(void* const* d_in, const int* in_sizes, int n_in,
                              void* d_out, int out_size) {
    const float* x  = (const float*)d_in[0];
    const float* xa = (const float*)d_in[1];
    const float* W  = (const float*)d_in[2];
    float* out = (float*)d_out;

    float *gx = nullptr, *gxa = nullptr;
    cudaGetSymbolAddress((void**)&gx,  g_x);
    cudaGetSymbolAddress((void**)&gxa, g_xa);

    dim3 grid(B_ * M_ * NK_);   // 2048 blocks
    dim3 block(128);            // 4 warps per unit

    // Layer 0: stage shift s = 0 (contiguous groups)
    ncn_layer<<<grid, block>>>(x, xa, W, gx, gxa, 0);
    // Layer 1: stage shift s = 1 (block = (g + o) % m), writes final output
    ncn_layer<<<grid, block>>>(gx, gxa, W + 2 * E_, out, out + BNE_, 1);
}

// round 9
// speedup vs baseline: 1.5432x; 1.0856x over previous
#include <cuda_runtime.h>

// Problem constants (fixed by the reference)
#define B_     4
#define N_     4096
#define E_     128
#define CACHE_ 32
#define NK_    4
#define CE_    32      // channels per unit (E / NK)
#define M_     128     // N / CACHE
#define BNE_   (B_*N_*E_)
#define NW_    2       // warps per unit
#define CPW_   16      // channels per warp
#define KP_    8       // packed channel pairs per warp

// Inter-layer scratch (device globals: no allocation in kernel_launch)
__device__ float g_x [BNE_];
__device__ float g_xa[BNE_];

typedef unsigned long long u64;

__device__ __forceinline__ float tanh_fast(float x) {
    float y;
    asm("tanh.approx.f32 %0, %1;" : "=f"(y) : "f"(x));
    return y;
}
__device__ __forceinline__ u64 pk(float lo, float hi) {
    u64 r; asm("mov.b64 %0, {%1, %2};" : "=l"(r) : "f"(lo), "f"(hi)); return r;
}
__device__ __forceinline__ void upk(u64 x, float& lo, float& hi) {
    asm("mov.b64 {%0, %1}, %2;" : "=f"(lo), "=f"(hi) : "l"(x));
}
__device__ __forceinline__ u64 fma2(u64 a, u64 b, u64 c) {
    u64 d; asm("fma.rn.f32x2 %0, %1, %2, %3;" : "=l"(d) : "l"(a), "l"(b), "l"(c)); return d;
}
__device__ __forceinline__ u64 mul2(u64 a, u64 b) {
    u64 d; asm("mul.rn.f32x2 %0, %1, %2;" : "=l"(d) : "l"(a), "l"(b)); return d;
}
__device__ __forceinline__ u64 add2(u64 a, u64 b) {
    u64 d; asm("add.rn.f32x2 %0, %1, %2;" : "=l"(d) : "l"(a), "l"(b)); return d;
}
__device__ __forceinline__ unsigned smem_u32(const void* p) {
    return (unsigned)__cvta_generic_to_shared(p);
}

// 2 warps per (b,g,n) unit, NO per-step __syncthreads. Warp w owns channels
// [w*16,w*16+16) as 8 packed pairs. Rescaled state u2=(xi/2)/0.9^j,
// v2=(xa/2)/0.9^j. Linear-split partial running dots per warp:
// X2w=(Ax_w,Bx_w), A2w=(Aa_w,Ba_w). Each step the warp publishes X2w
// (STS.64 + st.release counter); partner spins ld.acquire (skew provably <=1,
// 2-slot buffer safe). sim = (Ax_own+Ax_partner)[lane] + shfl(Bx_tot, j).
// X' = .9X+.09A+.01S with P2 precomputed off the critical path.
__global__ void __launch_bounds__(64, 14)
ncn_layer(const float* __restrict__ X, const float* __restrict__ XA,
          const float* __restrict__ W,         // 256 floats: Wi[4][32], Wj[4][32]
          float* __restrict__ YX, float* __restrict__ YA,
          int s)                                // group-index stride (0 or 1)
{
    __shared__ float tile[CACHE_][CACHE_ + 1];
    __shared__ u64 ebuf[2][NW_][CACHE_];        // [slot parity][warp][lane]
    __shared__ __align__(16) u64 sW4[CE_];      // (Wi2,Wj2) interleaved, 16 pairs
    __shared__ unsigned sflag[2 * 8];           // padded flags, one per warp

    const int t    = threadIdx.x;
    const int w    = t >> 5;                    // warp in block (0/1)
    const int lane = t & 31;                    // row-in-group
    const int blk  = blockIdx.x;                // 0 .. 2047
    const int n    = blk & (NK_ - 1);
    const int g    = (blk >> 2) & (M_ - 1);
    const int b    = blk >> 9;

    if (t < 2) sflag[t * 8] = 0;
    if (t < CE_ / 2) {
        int c = n * CE_ + 2 * t;
        sW4[2 * t]     = pk(W[c],      W[c + 1]);       // (Wi_c0, Wi_c1)
        sW4[2 * t + 1] = pk(W[E_ + c], W[E_ + c + 1]);  // (Wj_c0, Wj_c1)
    }

    const long long bBase    = (long long)b * N_ * E_;
    const long long chanBase = (long long)n * CE_ + lane;
    const int cw = w * CPW_;                    // this warp's first channel
    const int kw = cw >> 1;                     // first pair index
    const ulonglong2* sWv = reinterpret_cast<const ulonglong2*>(sW4);
    const unsigned flagSelf  = smem_u32(&sflag[w * 8]);
    const unsigned flagOther = smem_u32(&sflag[(1 - w) * 8]);

    u64 u2[KP_], v2[KP_];

    // ---- gather xi tile: warp w loads rows [w*16, w*16+16), coalesced ----
    #pragma unroll
    for (int r = 0; r < CPW_; ++r) {
        int rr  = cw + r;
        int row = ((g + rr * s) & (M_ - 1)) * CACHE_ + rr;
        tile[rr][lane] = X[bBase + (long long)row * E_ + chanBase];
    }
    __syncthreads();
    #pragma unroll
    for (int k = 0; k < KP_; ++k)
        u2[k] = pk(0.5f * tile[lane][cw + 2 * k], 0.5f * tile[lane][cw + 2 * k + 1]);
    __syncthreads();

    // ---- gather xa tile ----
    #pragma unroll
    for (int r = 0; r < CPW_; ++r) {
        int rr  = cw + r;
        int row = ((g + rr * s) & (M_ - 1)) * CACHE_ + rr;
        tile[rr][lane] = XA[bBase + (long long)row * E_ + chanBase];
    }
    __syncthreads();
    #pragma unroll
    for (int k = 0; k < KP_; ++k)
        v2[k] = pk(0.5f * tile[lane][cw + 2 * k], 0.5f * tile[lane][cw + 2 * k + 1]);

    const u64 K09  = pk(0.9f,  0.9f);
    const u64 K01  = pk(0.1f,  0.1f);
    const u64 K009 = pk(0.09f, 0.09f);
    const u64 K001 = pk(0.01f, 0.01f);
    const u64 Z    = pk(0.f, 0.f);

    // ---- initial partials: X2w=(Ax_w,Bx_w), A2w=(Aa_w,Ba_w) ----
    u64 X2w, A2w, P2;
    {
        u64 ax = Z, bx = Z, aa = Z, ba = Z;
        #pragma unroll
        for (int k = 0; k < KP_; ++k) {
            ulonglong2 ww = sWv[kw + k];        // (Wi2, Wj2)
            ax = fma2(u2[k], ww.x, ax);
            bx = fma2(u2[k], ww.y, bx);
            aa = fma2(v2[k], ww.x, aa);
            ba = fma2(v2[k], ww.y, ba);
        }
        float l, h, Ax, Bx, Aa, Ba;
        upk(ax, l, h); Ax = 2.f * (l + h);
        upk(bx, l, h); Bx = 2.f * (l + h);
        upk(aa, l, h); Aa = 2.f * (l + h);
        upk(ba, l, h); Ba = 2.f * (l + h);
        X2w = pk(Ax, Bx);
        A2w = pk(Aa, Ba);
        P2  = fma2(X2w, K09, mul2(A2w, K009));  // .9X + .09A for step 0
    }
    // publish step-0 data: data store, then release-store counter = 1
    ebuf[0][w][lane] = X2w;
    asm volatile("st.release.cta.shared.b32 [%0], %1;"
                 :: "r"(flagSelf), "r"(1u) : "memory");

    float sc = 1.0f;                  // 0.9^j
    float cj = 0.05f / 0.9f;          // 0.05 / 0.9^(j+1)

    // ---- 32-step recurrence (flag-synced, no barriers) ----
    #pragma unroll 1
    for (int j = 0; j < CACHE_; ++j) {
        const int p = j & 1;

        // wait until partner has published step-j data (skew <= 1 step)
        unsigned fl;
        do {
            asm volatile("ld.acquire.cta.shared.b32 %0, [%1];"
                         : "=r"(fl) : "r"(flagOther) : "memory");
        } while (fl < (unsigned)(j + 1));

        u64 oth  = ebuf[p][1 - w][lane];        // partner (Ax_o,Bx_o)
        u64 tot2 = add2(X2w, oth);              // (Ax_tot, Bx_tot) per lane
        float Axt, Bxt; upk(tot2, Axt, Bxt);
        float sim = Axt + __shfl_sync(0xffffffffu, Bxt, j);

        u64 sim2 = pk(sim, sim);
        u64 s2   = pk(sc, sc);
        u64 c2   = pk(cj, cj);
        u64 SA = Z, SB = Z, DA = Z, DB = Z;
        #pragma unroll
        for (int k = 0; k < KP_; ++k) {
            u64 uj = __shfl_sync(0xffffffffu, u2[k], j);    // pre-update row j
            u64 T  = mul2(s2, fma2(sim2, uj, u2[k]));       // true-scale T
            float t0, t1; upk(T, t0, t1);
            u64 F = pk(tanh_fast(t0), tanh_fast(t1));
            ulonglong2 ww = sWv[kw + k];                     // one LDS.128
            if (k & 1) { SB = fma2(F, ww.x, SB); DB = fma2(F, ww.y, DB); }
            else       { SA = fma2(F, ww.x, SA); DA = fma2(F, ww.y, DA); }
            v2[k] = fma2(c2,  F,     v2[k]);                // ~xa update
            u2[k] = fma2(K01, v2[k], u2[k]);                // ~xi update
        }
        float l, h, SF, DF;
        { u64 q = add2(SA, SB); upk(q, l, h); SF = l + h; }
        { u64 q = add2(DA, DB); upk(q, l, h); DF = l + h; }
        u64 S2 = pk(SF, DF);

        X2w = fma2(S2, K001, P2);                           // X' = .9X+.09A+.01S
        ebuf[p ^ 1][w][lane] = X2w;                         // publish data
        asm volatile("st.release.cta.shared.b32 [%0], %1;"  // then counter=j+2
                     :: "r"(flagSelf), "r"((unsigned)(j + 2)) : "memory");
        A2w = fma2(A2w, K09, mul2(S2, K01));                // off-chain
        P2  = fma2(X2w, K09, mul2(A2w, K009));              // for next step

        sc *= 0.9f;
        cj *= (1.0f / 0.9f);
    }

    const float fscale = 2.0f * sc;   // undo half-scale and 0.9^32 rescale

    // ---- scatter yi (syncthreads re-aligns the <=1-step skew) ----
    __syncthreads();
    #pragma unroll
    for (int k = 0; k < KP_; ++k) {
        float l, h; upk(u2[k], l, h);
        tile[lane][cw + 2 * k]     = fscale * l;
        tile[lane][cw + 2 * k + 1] = fscale * h;
    }
    __syncthreads();
    #pragma unroll
    for (int r = 0; r < CPW_; ++r) {
        int rr  = cw + r;
        int row = ((g + rr * s) & (M_ - 1)) * CACHE_ + rr;
        YX[bBase + (long long)row * E_ + chanBase] = tile[rr][lane];
    }
    __syncthreads();

    // ---- scatter ya ----
    #pragma unroll
    for (int k = 0; k < KP_; ++k) {
        float l, h; upk(v2[k], l, h);
        tile[lane][cw + 2 * k]     = fscale * l;
        tile[lane][cw + 2 * k + 1] = fscale * h;
    }
    __syncthreads();
    #pragma unroll
    for (int r = 0; r < CPW_; ++r) {
        int rr  = cw + r;
        int row = ((g + rr * s) & (M_ - 1)) * CACHE_ + rr;
        YA[bBase + (long long)row * E_ + chanBase] = tile[rr][lane];
    }
}

extern "C" void kernel_launch(void* const* d_in, const int* in_sizes, int n_in,
                              void* d_out, int out_size) {
    const float* x  = (const float*)d_in[0];
    const float* xa = (const float*)d_in[1];
    const float* W  = (const float*)d_in[2];
    float* out = (float*)d_out;

    float *gx = nullptr, *gxa = nullptr;
    cudaGetSymbolAddress((void**)&gx,  g_x);
    cudaGetSymbolAddress((void**)&gxa, g_xa);

    dim3 grid(B_ * M_ * NK_);   // 2048 blocks
    dim3 block(64);             // 2 warps per unit

    // Layer 0: stage shift s = 0 (contiguous groups)
    ncn_layer<<<grid, block>>>(x, xa, W, gx, gxa, 0);
    // Layer 1: stage shift s = 1 (block = (g + o) % m), writes final output
    ncn_layer<<<grid, block>>>(gx, gxa, W + 2 * E_, out, out + BNE_, 1);
}

// round 10
// speedup vs baseline: 1.6231x; 1.0518x over previous
#include <cuda_runtime.h>

// Problem constants (fixed by the reference)
#define B_     4
#define N_     4096
#define E_     128
#define CACHE_ 32
#define NK_    4
#define CE_    32      // channels per unit (E / NK)
#define M_     128     // N / CACHE
#define BNE_   (B_*N_*E_)
#define NW_    2       // warps per unit
#define CPW_   16      // channels per warp
#define KP_    8       // packed channel pairs per warp

// Inter-layer scratch (device globals: no allocation in kernel_launch)
__device__ float g_x [BNE_];
__device__ float g_xa[BNE_];

typedef unsigned long long u64;

__device__ __forceinline__ float tanh_fast(float x) {
    float y;
    asm("tanh.approx.f32 %0, %1;" : "=f"(y) : "f"(x));
    return y;
}
__device__ __forceinline__ u64 pk(float lo, float hi) {
    u64 r; asm("mov.b64 %0, {%1, %2};" : "=l"(r) : "f"(lo), "f"(hi)); return r;
}
__device__ __forceinline__ void upk(u64 x, float& lo, float& hi) {
    asm("mov.b64 {%0, %1}, %2;" : "=f"(lo), "=f"(hi) : "l"(x));
}
__device__ __forceinline__ u64 fma2(u64 a, u64 b, u64 c) {
    u64 d; asm("fma.rn.f32x2 %0, %1, %2, %3;" : "=l"(d) : "l"(a), "l"(b), "l"(c)); return d;
}
__device__ __forceinline__ u64 mul2(u64 a, u64 b) {
    u64 d; asm("mul.rn.f32x2 %0, %1, %2;" : "=l"(d) : "l"(a), "l"(b)); return d;
}
__device__ __forceinline__ u64 add2(u64 a, u64 b) {
    u64 d; asm("add.rn.f32x2 %0, %1, %2;" : "=l"(d) : "l"(a), "l"(b)); return d;
}

// 2 warps per (b,g,n) unit. lane = row-in-group. Warp w owns channels
// [w*16,w*16+16) as 8 packed pairs. Rescaled state u2=(xi/2)/0.9^j,
// v2=(xa/2)/0.9^j. Linear-split partial running dots per warp:
// X2w=(Ax_w,Bx_w), A2w=(Aa_w,Ba_w); sim = (Ax_tot)[lane] + shfl(Bx_tot, j).
// ROW MIRROR: instead of 8x 64-bit shfl per step to broadcast row j's state,
// lane j+1 writes its updated pairs to a per-warp smem mirror (4 STS.128)
// at the end of step j; all lanes read them (4 LDS.128 broadcast) at step
// j+1. The per-step __syncthreads orders it. Double-buffered by parity.
// X' = .9X+.09A+.01S with P2 = .9X+.09A precomputed off the critical path.
__global__ void __launch_bounds__(64, 14)
ncn_layer(const float* __restrict__ X, const float* __restrict__ XA,
          const float* __restrict__ W,         // 256 floats: Wi[4][32], Wj[4][32]
          float* __restrict__ YX, float* __restrict__ YA,
          int s)                                // group-index stride (0 or 1)
{
    __shared__ float tile[CACHE_][CACHE_ + 1];
    __shared__ u64 ebuf[2][NW_][CACHE_];        // [parity][warp][lane] = (Ax_w,Bx_w)
    __shared__ __align__(16) u64 sW4[CE_];      // (Wi2,Wj2) interleaved, 16 pairs
    __shared__ __align__(16) u64 mir[2][NW_][KP_];  // row-j state mirror

    const int t    = threadIdx.x;
    const int w    = t >> 5;                    // warp in block (0/1)
    const int lane = t & 31;                    // row-in-group
    const int blk  = blockIdx.x;                // 0 .. 2047
    const int n    = blk & (NK_ - 1);
    const int g    = (blk >> 2) & (M_ - 1);
    const int b    = blk >> 9;

    if (t < CE_ / 2) {
        int c = n * CE_ + 2 * t;
        sW4[2 * t]     = pk(W[c],      W[c + 1]);       // (Wi_c0, Wi_c1)
        sW4[2 * t + 1] = pk(W[E_ + c], W[E_ + c + 1]);  // (Wj_c0, Wj_c1)
    }

    const long long bBase    = (long long)b * N_ * E_;
    const long long chanBase = (long long)n * CE_ + lane;
    const int cw = w * CPW_;                    // this warp's first channel
    const int kw = cw >> 1;                     // first weight-pair index
    const ulonglong2* sWv = reinterpret_cast<const ulonglong2*>(sW4);

    u64 u2[KP_], v2[KP_];

    // ---- gather xi tile: warp w loads rows [w*16, w*16+16), coalesced ----
    #pragma unroll
    for (int r = 0; r < CPW_; ++r) {
        int rr  = cw + r;
        int row = ((g + rr * s) & (M_ - 1)) * CACHE_ + rr;
        tile[rr][lane] = X[bBase + (long long)row * E_ + chanBase];
    }
    __syncthreads();
    #pragma unroll
    for (int k = 0; k < KP_; ++k)
        u2[k] = pk(0.5f * tile[lane][cw + 2 * k], 0.5f * tile[lane][cw + 2 * k + 1]);
    __syncthreads();

    // ---- gather xa tile ----
    #pragma unroll
    for (int r = 0; r < CPW_; ++r) {
        int rr  = cw + r;
        int row = ((g + rr * s) & (M_ - 1)) * CACHE_ + rr;
        tile[rr][lane] = XA[bBase + (long long)row * E_ + chanBase];
    }
    __syncthreads();
    #pragma unroll
    for (int k = 0; k < KP_; ++k)
        v2[k] = pk(0.5f * tile[lane][cw + 2 * k], 0.5f * tile[lane][cw + 2 * k + 1]);

    const u64 K09  = pk(0.9f,  0.9f);
    const u64 K01  = pk(0.1f,  0.1f);
    const u64 K009 = pk(0.09f, 0.09f);
    const u64 K001 = pk(0.01f, 0.01f);
    const u64 Z    = pk(0.f, 0.f);

    // ---- initial partials: X2w=(Ax_w,Bx_w), A2w=(Aa_w,Ba_w) ----
    u64 X2w, A2w, P2;
    {
        u64 ax = Z, bx = Z, aa = Z, ba = Z;
        #pragma unroll
        for (int k = 0; k < KP_; ++k) {
            ulonglong2 ww = sWv[kw + k];        // (Wi2, Wj2)
            ax = fma2(u2[k], ww.x, ax);
            bx = fma2(u2[k], ww.y, bx);
            aa = fma2(v2[k], ww.x, aa);
            ba = fma2(v2[k], ww.y, ba);
        }
        float l, h, Ax, Bx, Aa, Ba;
        upk(ax, l, h); Ax = 2.f * (l + h);
        upk(bx, l, h); Bx = 2.f * (l + h);
        upk(aa, l, h); Aa = 2.f * (l + h);
        upk(ba, l, h); Ba = 2.f * (l + h);
        X2w = pk(Ax, Bx);
        A2w = pk(Aa, Ba);
        P2  = fma2(X2w, K09, mul2(A2w, K009));  // .9X + .09A for step 0
    }
    ebuf[0][w][lane] = X2w;                     // publish partials for step 0
    if (lane == 0) {                            // mirror row 0's initial state
        #pragma unroll
        for (int k2 = 0; k2 < KP_ / 2; ++k2) {
            ulonglong2 tv; tv.x = u2[2 * k2]; tv.y = u2[2 * k2 + 1];
            *reinterpret_cast<ulonglong2*>(&mir[0][w][2 * k2]) = tv;
        }
    }
    __syncthreads();

    float sc = 1.0f;                  // 0.9^j
    float cj = 0.05f / 0.9f;          // 0.05 / 0.9^(j+1)

    // ---- 32-step recurrence ----
    #pragma unroll 1
    for (int j = 0; j < CACHE_; ++j) {
        const int p = j & 1;

        // row-j pre-update state from the mirror (uniform broadcast LDS.128)
        ulonglong2 ujv[KP_ / 2];
        #pragma unroll
        for (int k2 = 0; k2 < KP_ / 2; ++k2)
            ujv[k2] = *reinterpret_cast<const ulonglong2*>(&mir[p][w][2 * k2]);

        // sim = Ax_tot[lane] + Bx_tot[j]
        u64 oth  = ebuf[p][1 - w][lane];
        u64 tot2 = add2(X2w, oth);
        float Axt, Bxt; upk(tot2, Axt, Bxt);
        float sim = Axt + __shfl_sync(0xffffffffu, Bxt, j);

        u64 sim2 = pk(sim, sim);
        u64 s2   = pk(sc, sc);
        u64 c2   = pk(cj, cj);
        u64 SA = Z, SB = Z, DA = Z, DB = Z;
        #pragma unroll
        for (int k = 0; k < KP_; ++k) {
            u64 uj = (k & 1) ? ujv[k >> 1].y : ujv[k >> 1].x;
            u64 T  = mul2(s2, fma2(sim2, uj, u2[k]));       // true-scale T
            float t0, t1; upk(T, t0, t1);
            u64 F = pk(tanh_fast(t0), tanh_fast(t1));
            ulonglong2 ww = sWv[kw + k];                     // one LDS.128
            if (k & 1) { SB = fma2(F, ww.x, SB); DB = fma2(F, ww.y, DB); }
            else       { SA = fma2(F, ww.x, SA); DA = fma2(F, ww.y, DA); }
            v2[k] = fma2(c2,  F,     v2[k]);                // ~xa update
            u2[k] = fma2(K01, v2[k], u2[k]);                // ~xi update
        }
        float l, h, SF, DF;
        { u64 q = add2(SA, SB); upk(q, l, h); SF = l + h; }
        { u64 q = add2(DA, DB); upk(q, l, h); DF = l + h; }
        u64 S2 = pk(SF, DF);

        X2w = fma2(S2, K001, P2);                           // X' = .9X+.09A+.01S
        ebuf[p ^ 1][w][lane] = X2w;                         // publish partials
        A2w = fma2(A2w, K09, mul2(S2, K01));                // off-chain
        P2  = fma2(X2w, K09, mul2(A2w, K009));              // for next step

        // next source row (lane j+1) publishes its updated state
        if (lane == j + 1) {
            #pragma unroll
            for (int k2 = 0; k2 < KP_ / 2; ++k2) {
                ulonglong2 tv; tv.x = u2[2 * k2]; tv.y = u2[2 * k2 + 1];
                *reinterpret_cast<ulonglong2*>(&mir[p ^ 1][w][2 * k2]) = tv;
            }
        }
        __syncthreads();                                    // one bar per step

        sc *= 0.9f;
        cj *= (1.0f / 0.9f);
    }

    const float fscale = 2.0f * sc;   // undo half-scale and 0.9^32 rescale

    // ---- scatter yi ----
    #pragma unroll
    for (int k = 0; k < KP_; ++k) {
        float l, h; upk(u2[k], l, h);
        tile[lane][cw + 2 * k]     = fscale * l;
        tile[lane][cw + 2 * k + 1] = fscale * h;
    }
    __syncthreads();
    #pragma unroll
    for (int r = 0; r < CPW_; ++r) {
        int rr  = cw + r;
        int row = ((g + rr * s) & (M_ - 1)) * CACHE_ + rr;
        YX[bBase + (long long)row * E_ + chanBase] = tile[rr][lane];
    }
    __syncthreads();

    // ---- scatter ya ----
    #pragma unroll
    for (int k = 0; k < KP_; ++k) {
        float l, h; upk(v2[k], l, h);
        tile[lane][cw + 2 * k]     = fscale * l;
        tile[lane][cw + 2 * k + 1] = fscale * h;
    }
    __syncthreads();
    #pragma unroll
    for (int r = 0; r < CPW_; ++r) {
        int rr  = cw + r;
        int row = ((g + rr * s) & (M_ - 1)) * CACHE_ + rr;
        YA[bBase + (long long)row * E_ + chanBase] = tile[rr][lane];
    }
}

extern "C" void kernel_launch(void* const* d_in, const int* in_sizes, int n_in,
                              void* d_out, int out_size) {
    const float* x  = (const float*)d_in[0];
    const float* xa = (const float*)d_in[1];
    const float* W  = (const float*)d_in[2];
    float* out = (float*)d_out;

    float *gx = nullptr, *gxa = nullptr;
    cudaGetSymbolAddress((void**)&gx,  g_x);
    cudaGetSymbolAddress((void**)&gxa, g_xa);

    dim3 grid(B_ * M_ * NK_);   // 2048 blocks
    dim3 block(64);             // 2 warps per unit

    // Layer 0: stage shift s = 0 (contiguous groups)
    ncn_layer<<<grid, block>>>(x, xa, W, gx, gxa, 0);
    // Layer 1: stage shift s = 1 (block = (g + o) % m), writes final output
    ncn_layer<<<grid, block>>>(gx, gxa, W + 2 * E_, out, out + BNE_, 1);
}